// round 1
// baseline (speedup 1.0000x reference)
#include <cuda_runtime.h>
#include <cuda_bf16.h>

// Problem constants: B=8, T=1024, C=768, H=12, HD=64
//   M = B*T = 8192, QKV N = 2304, proj N = 768, K = 768
// Scratch (device globals; no allocation allowed):
//   g_q/g_k/g_v : [B,H,T,64]  (12*8=96 "bh" slices of 1024x64)
//   g_y         : [B,T,768]   attention output before projection

__device__ float g_q[6291456];
__device__ float g_k[6291456];
__device__ float g_v[6291456];
__device__ float g_y[6291456];

// ---------------------------------------------------------------------------
// Kernel 1: QKV GEMM.  qkv = x @ w_attn + b_attn, scattered into q/k/v
// [B,H,T,64] layouts.  Tiles: 64x64 per block, K-step 16, 256 threads,
// 4x4 micro-tile per thread.
// ---------------------------------------------------------------------------
__global__ __launch_bounds__(256) void gemm_qkv_kernel(
    const float* __restrict__ x, const float* __restrict__ w,
    const float* __restrict__ bias)
{
    const int K = 768, N = 2304;
    __shared__ float As[16][64];   // [k][m]
    __shared__ float Bs[16][64];   // [k][n]
    const int tid = threadIdx.x;
    const int tx = tid & 15, ty = tid >> 4;
    const int m0 = blockIdx.y * 64, n0 = blockIdx.x * 64;
    const int arow = tid >> 2;          // 0..63
    const int acol = (tid & 3) * 4;     // 0,4,8,12
    const int brow = tid >> 4;          // 0..15
    const int bcol = (tid & 15) * 4;    // 0..60
    float acc[4][4] = {};
    for (int k0 = 0; k0 < K; k0 += 16) {
        float4 av = *(const float4*)(x + (size_t)(m0 + arow) * K + k0 + acol);
        float4 bv = *(const float4*)(w + (size_t)(k0 + brow) * N + n0 + bcol);
        __syncthreads();
        As[acol + 0][arow] = av.x;
        As[acol + 1][arow] = av.y;
        As[acol + 2][arow] = av.z;
        As[acol + 3][arow] = av.w;
        *(float4*)&Bs[brow][bcol] = bv;
        __syncthreads();
#pragma unroll
        for (int k = 0; k < 16; k++) {
            float4 a = *(const float4*)&As[k][ty * 4];
            float4 b = *(const float4*)&Bs[k][tx * 4];
            float af[4] = {a.x, a.y, a.z, a.w};
            float bf[4] = {b.x, b.y, b.z, b.w};
#pragma unroll
            for (int i = 0; i < 4; i++)
#pragma unroll
                for (int j = 0; j < 4; j++)
                    acc[i][j] = fmaf(af[i], bf[j], acc[i][j]);
        }
    }
    // Epilogue: bias + scatter to [B,H,T,64]
#pragma unroll
    for (int i = 0; i < 4; i++) {
        int m = m0 + ty * 4 + i;
        int bb = m >> 10, t = m & 1023;
#pragma unroll
        for (int j = 0; j < 4; j++) {
            int n = n0 + tx * 4 + j;
            float v = acc[i][j] + bias[n];
            int which = n / 768;
            int c = n - which * 768;
            int hh = c >> 6, d = c & 63;
            float* dst = (which == 0) ? g_q : (which == 1) ? g_k : g_v;
            dst[((((size_t)bb * 12 + hh) << 10) + t) * 64 + d] = v;
        }
    }
}

// ---------------------------------------------------------------------------
// Kernel 2: causal flash attention, fp32.
// Grid: (16 q-tiles, 96 bh).  Block 256 threads.
// q-tile = 64 rows; K/V tiles of 32 rows; online softmax.
// ---------------------------------------------------------------------------
__global__ __launch_bounds__(256) void attn_kernel()
{
    __shared__ float Qs[64][64];   // [q][d]
    __shared__ float Kt[64][36];   // [d][k]   padded pitch (36: float4-able, conflict-light)
    __shared__ float Vs[32][64];   // [k][d]
    __shared__ float Ps[64][36];   // [q][k]   scores -> probabilities
    __shared__ float s_m[64], s_l[64], s_f[64];

    const int tid = threadIdx.x;
    const int qi = blockIdx.x;       // 0..15
    const int bh = blockIdx.y;       // 0..95
    const int q0 = qi * 64;
    const float* qb = g_q + (size_t)bh * 65536;
    const float* kb = g_k + (size_t)bh * 65536;
    const float* vb = g_v + (size_t)bh * 65536;

    // Load Q tile (4096 floats, float4)
#pragma unroll
    for (int r = 0; r < 4; r++) {
        int idx = tid + r * 256;
        int q = idx >> 4, d4 = (idx & 15) * 4;
        *(float4*)&Qs[q][d4] = *(const float4*)(qb + (q0 + q) * 64 + d4);
    }
    if (tid < 64) { s_m[tid] = -1e30f; s_l[tid] = 0.0f; }

    const int tx = tid & 15, ty = tid >> 4;  // PV / O mapping: 4q x 4d
    const int tk = tid & 7,  tq = tid >> 3;  // S  mapping:     2q x 4k
    float o[4][4] = {};

    const int ktiles = (q0 >> 5) + 2;        // cover k <= q0+63
    for (int kt = 0; kt < ktiles; kt++) {
        const int k0 = kt * 32;
        __syncthreads();                     // prior tile's smem reads done
        // Load K (transposed) and V: 32x64 each
#pragma unroll
        for (int r = 0; r < 2; r++) {
            int idx = tid + r * 256;
            int kk = idx >> 4, d4 = (idx & 15) * 4;
            float4 kv = *(const float4*)(kb + (k0 + kk) * 64 + d4);
            Kt[d4 + 0][kk] = kv.x;
            Kt[d4 + 1][kk] = kv.y;
            Kt[d4 + 2][kk] = kv.z;
            Kt[d4 + 3][kk] = kv.w;
            *(float4*)&Vs[kk][d4] = *(const float4*)(vb + (k0 + kk) * 64 + d4);
        }
        __syncthreads();

        // S = (Q K^T) * scale, causal mask, into Ps
        float s[2][4] = {};
#pragma unroll
        for (int d = 0; d < 64; d += 4) {
            float4 qa = *(const float4*)&Qs[2 * tq + 0][d];
            float4 qc = *(const float4*)&Qs[2 * tq + 1][d];
            float qav[4] = {qa.x, qa.y, qa.z, qa.w};
            float qcv[4] = {qc.x, qc.y, qc.z, qc.w};
#pragma unroll
            for (int dd = 0; dd < 4; dd++) {
                float4 kv = *(const float4*)&Kt[d + dd][4 * tk];
                float kf[4] = {kv.x, kv.y, kv.z, kv.w};
#pragma unroll
                for (int j = 0; j < 4; j++) {
                    s[0][j] = fmaf(qav[dd], kf[j], s[0][j]);
                    s[1][j] = fmaf(qcv[dd], kf[j], s[1][j]);
                }
            }
        }
#pragma unroll
        for (int i = 0; i < 2; i++) {
            int qg = q0 + 2 * tq + i;
#pragma unroll
            for (int j = 0; j < 4; j++) {
                int kg = k0 + 4 * tk + j;
                float v = s[i][j] * 0.125f;  // 1/sqrt(64)
                Ps[2 * tq + i][4 * tk + j] = (kg > qg) ? -1e30f : v;
            }
        }
        __syncthreads();

        // Online softmax, one thread per q-row
        if (tid < 64) {
            float mold = s_m[tid];
            float mt = mold;
#pragma unroll
            for (int kk = 0; kk < 32; kk++) mt = fmaxf(mt, Ps[tid][kk]);
            float f = __expf(mold - mt);
            float ls = 0.0f;
#pragma unroll
            for (int kk = 0; kk < 32; kk++) {
                float p = __expf(Ps[tid][kk] - mt);
                Ps[tid][kk] = p;
                ls += p;
            }
            s_m[tid] = mt;
            s_l[tid] = s_l[tid] * f + ls;
            s_f[tid] = f;
        }
        __syncthreads();

        // O = O*f + P @ V
        float fr[4];
#pragma unroll
        for (int i = 0; i < 4; i++) fr[i] = s_f[4 * ty + i];
#pragma unroll
        for (int i = 0; i < 4; i++)
#pragma unroll
            for (int j = 0; j < 4; j++) o[i][j] *= fr[i];
#pragma unroll
        for (int kk = 0; kk < 32; kk++) {
            float4 vv = *(const float4*)&Vs[kk][4 * tx];
            float vf[4] = {vv.x, vv.y, vv.z, vv.w};
            float pr[4];
#pragma unroll
            for (int i = 0; i < 4; i++) pr[i] = Ps[4 * ty + i][kk];
#pragma unroll
            for (int i = 0; i < 4; i++)
#pragma unroll
                for (int j = 0; j < 4; j++)
                    o[i][j] = fmaf(pr[i], vf[j], o[i][j]);
        }
    }

    // Normalize and write to g_y in [B,T,C] layout (un-transpose for free)
    const int b = bh / 12, h = bh - b * 12;
#pragma unroll
    for (int i = 0; i < 4; i++) {
        int q = 4 * ty + i;
        float inv = 1.0f / s_l[q];
        int t = q0 + q;
        float* dst = g_y + ((size_t)(b * 1024 + t)) * 768 + h * 64 + 4 * tx;
        float4 out4 = make_float4(o[i][0] * inv, o[i][1] * inv,
                                  o[i][2] * inv, o[i][3] * inv);
        *(float4*)dst = out4;
    }
}

// ---------------------------------------------------------------------------
// Kernel 3: output projection.  out = g_y @ w_proj + b_proj.
// Same tiling as kernel 1.
// ---------------------------------------------------------------------------
__global__ __launch_bounds__(256) void gemm_proj_kernel(
    const float* __restrict__ w, const float* __restrict__ bias,
    float* __restrict__ out)
{
    const int K = 768, N = 768;
    __shared__ float As[16][64];
    __shared__ float Bs[16][64];
    const int tid = threadIdx.x;
    const int tx = tid & 15, ty = tid >> 4;
    const int m0 = blockIdx.y * 64, n0 = blockIdx.x * 64;
    const int arow = tid >> 2;
    const int acol = (tid & 3) * 4;
    const int brow = tid >> 4;
    const int bcol = (tid & 15) * 4;
    float acc[4][4] = {};
    for (int k0 = 0; k0 < K; k0 += 16) {
        float4 av = *(const float4*)(g_y + (size_t)(m0 + arow) * K + k0 + acol);
        float4 bv = *(const float4*)(w + (size_t)(k0 + brow) * N + n0 + bcol);
        __syncthreads();
        As[acol + 0][arow] = av.x;
        As[acol + 1][arow] = av.y;
        As[acol + 2][arow] = av.z;
        As[acol + 3][arow] = av.w;
        *(float4*)&Bs[brow][bcol] = bv;
        __syncthreads();
#pragma unroll
        for (int k = 0; k < 16; k++) {
            float4 a = *(const float4*)&As[k][ty * 4];
            float4 b = *(const float4*)&Bs[k][tx * 4];
            float af[4] = {a.x, a.y, a.z, a.w};
            float bf[4] = {b.x, b.y, b.z, b.w};
#pragma unroll
            for (int i = 0; i < 4; i++)
#pragma unroll
                for (int j = 0; j < 4; j++)
                    acc[i][j] = fmaf(af[i], bf[j], acc[i][j]);
        }
    }
#pragma unroll
    for (int i = 0; i < 4; i++) {
        int m = m0 + ty * 4 + i;
#pragma unroll
        for (int j = 0; j < 4; j++) {
            int n = n0 + tx * 4 + j;
            out[(size_t)m * 768 + n] = acc[i][j] + bias[n];
        }
    }
}

// ---------------------------------------------------------------------------
extern "C" void kernel_launch(void* const* d_in, const int* in_sizes, int n_in,
                              void* d_out, int out_size)
{
    const float* x      = (const float*)d_in[0];
    const float* w_attn = (const float*)d_in[1];
    const float* b_attn = (const float*)d_in[2];
    const float* w_proj = (const float*)d_in[3];
    const float* b_proj = (const float*)d_in[4];
    float* out = (float*)d_out;

    gemm_qkv_kernel<<<dim3(36, 128), 256>>>(x, w_attn, b_attn);
    attn_kernel<<<dim3(16, 96), 256>>>();
    gemm_proj_kernel<<<dim3(12, 128), 256>>>(w_proj, b_proj, out);
}

// round 2
// speedup vs baseline: 1.9336x; 1.9336x over previous
#include <cuda_runtime.h>
#include <cuda_bf16.h>
#include <cstdint>

// Problem constants: B=8, T=1024, C=768, H=12, HD=64
// Scratch (device globals; no allocation allowed):
__device__ float g_q[6291456];
__device__ float g_k[6291456];
__device__ float g_v[6291456];
__device__ float g_y[6291456];

// ---------------------------------------------------------------------------
// TF32 helpers
// ---------------------------------------------------------------------------
__device__ __forceinline__ float to_tf32(float x) {
    uint32_t u;
    asm("cvt.rna.tf32.f32 %0, %1;" : "=r"(u) : "f"(x));
    return __uint_as_float(u);
}

__device__ __forceinline__ void mma_tf32(float* c, const uint32_t* a, const uint32_t* b) {
    asm volatile(
        "mma.sync.aligned.m16n8k8.row.col.f32.tf32.tf32.f32 "
        "{%0,%1,%2,%3},{%4,%5,%6,%7},{%8,%9},{%0,%1,%2,%3};"
        : "+f"(c[0]), "+f"(c[1]), "+f"(c[2]), "+f"(c[3])
        : "r"(a[0]), "r"(a[1]), "r"(a[2]), "r"(a[3]), "r"(b[0]), "r"(b[1]));
}

// ---------------------------------------------------------------------------
// TF32 tensor-core GEMM body: 128x64 block tile, K-step 32, 8 warps (4m x 2n),
// warp tile 32x32 built from m16n8k8 MMAs.
//   As[128][36]  (pitch 36 -> A-frag loads hit banks (4g+c)%32: conflict-free)
//   Bs[32][72]   (pitch 72 -> B-frag loads hit banks (8c+g)%32: conflict-free)
// acc[2][4][4] per thread. Caller provides row pointers + epilogue.
// ---------------------------------------------------------------------------
#define GEMM_TF32_BODY(APTR, LDA, BPTR, LDB, KDIM)                              \
    __shared__ float As[128][36];                                               \
    __shared__ float Bs[32][72];                                                \
    const int tid  = threadIdx.x;                                               \
    const int lane = tid & 31;                                                  \
    const int wid  = tid >> 5;                                                  \
    const int warp_m = wid >> 1, warp_n = wid & 1;                              \
    const int g = lane >> 2, tg = lane & 3;                                     \
    const int m0 = blockIdx.y * 128, n0 = blockIdx.x * 64;                      \
    float acc[2][4][4] = {};                                                    \
    const int a_row = tid >> 3, a_col = (tid & 7) * 4;                          \
    const int b_row = tid >> 4, b_col = (tid & 15) * 4;                         \
    for (int k0 = 0; k0 < (KDIM); k0 += 32) {                                   \
        float4 av[4];                                                           \
        _Pragma("unroll")                                                       \
        for (int r = 0; r < 4; r++)                                             \
            av[r] = *(const float4*)((APTR) + (size_t)(m0 + r * 32 + a_row) * (LDA) + k0 + a_col); \
        float4 bv[2];                                                           \
        _Pragma("unroll")                                                       \
        for (int r = 0; r < 2; r++)                                             \
            bv[r] = *(const float4*)((BPTR) + (size_t)(k0 + r * 16 + b_row) * (LDB) + n0 + b_col); \
        __syncthreads();                                                        \
        _Pragma("unroll")                                                       \
        for (int r = 0; r < 4; r++) {                                           \
            float* dst = &As[r * 32 + a_row][a_col];                            \
            dst[0] = to_tf32(av[r].x); dst[1] = to_tf32(av[r].y);               \
            dst[2] = to_tf32(av[r].z); dst[3] = to_tf32(av[r].w);               \
        }                                                                       \
        _Pragma("unroll")                                                       \
        for (int r = 0; r < 2; r++) {                                           \
            float* dst = &Bs[r * 16 + b_row][b_col];                            \
            dst[0] = to_tf32(bv[r].x); dst[1] = to_tf32(bv[r].y);               \
            dst[2] = to_tf32(bv[r].z); dst[3] = to_tf32(bv[r].w);               \
        }                                                                       \
        __syncthreads();                                                        \
        _Pragma("unroll")                                                       \
        for (int ks = 0; ks < 4; ks++) {                                        \
            const int kk = ks * 8;                                              \
            uint32_t afr[2][4], bfr[4][2];                                      \
            _Pragma("unroll")                                                   \
            for (int mt = 0; mt < 2; mt++) {                                    \
                const int mr = warp_m * 32 + mt * 16;                           \
                afr[mt][0] = __float_as_uint(As[mr + g][kk + tg]);              \
                afr[mt][1] = __float_as_uint(As[mr + g + 8][kk + tg]);          \
                afr[mt][2] = __float_as_uint(As[mr + g][kk + tg + 4]);          \
                afr[mt][3] = __float_as_uint(As[mr + g + 8][kk + tg + 4]);      \
            }                                                                   \
            _Pragma("unroll")                                                   \
            for (int nt = 0; nt < 4; nt++) {                                    \
                const int nc = warp_n * 32 + nt * 8;                            \
                bfr[nt][0] = __float_as_uint(Bs[kk + tg][nc + g]);              \
                bfr[nt][1] = __float_as_uint(Bs[kk + tg + 4][nc + g]);          \
            }                                                                   \
            _Pragma("unroll")                                                   \
            for (int mt = 0; mt < 2; mt++)                                      \
                _Pragma("unroll")                                               \
                for (int nt = 0; nt < 4; nt++)                                  \
                    mma_tf32(acc[mt][nt], afr[mt], bfr[nt]);                    \
        }                                                                       \
    }

// ---------------------------------------------------------------------------
// Kernel 1: QKV GEMM (M=8192, N=2304, K=768), epilogue scatters to
// q/k/v in [B,H,T,64] layout with bias.
// ---------------------------------------------------------------------------
__global__ __launch_bounds__(256) void gemm_qkv_tc(
    const float* __restrict__ x, const float* __restrict__ w,
    const float* __restrict__ bias)
{
    GEMM_TF32_BODY(x, 768, w, 2304, 768)

    // Epilogue: c0:(g,2tg) c1:(g,2tg+1) c2:(g+8,2tg) c3:(g+8,2tg+1)
#pragma unroll
    for (int mt = 0; mt < 2; mt++) {
#pragma unroll
        for (int nt = 0; nt < 4; nt++) {
#pragma unroll
            for (int e = 0; e < 4; e++) {
                int m = m0 + warp_m * 32 + mt * 16 + g + (e >> 1) * 8;
                int n = n0 + warp_n * 32 + nt * 8 + 2 * tg + (e & 1);
                float v = acc[mt][nt][e] + bias[n];
                int bb = m >> 10, t = m & 1023;
                int which = n / 768;
                int c = n - which * 768;
                int hh = c >> 6, d = c & 63;
                float* dst = (which == 0) ? g_q : (which == 1) ? g_k : g_v;
                dst[((((size_t)bb * 12 + hh) << 10) + t) * 64 + d] = v;
            }
        }
    }
}

// ---------------------------------------------------------------------------
// Kernel 3: output projection (M=8192, N=768, K=768), reads g_y, writes d_out.
// ---------------------------------------------------------------------------
__global__ __launch_bounds__(256) void gemm_proj_tc(
    const float* __restrict__ w, const float* __restrict__ bias,
    float* __restrict__ out)
{
    GEMM_TF32_BODY(g_y, 768, w, 768, 768)

#pragma unroll
    for (int mt = 0; mt < 2; mt++) {
#pragma unroll
        for (int nt = 0; nt < 4; nt++) {
#pragma unroll
            for (int e = 0; e < 4; e++) {
                int m = m0 + warp_m * 32 + mt * 16 + g + (e >> 1) * 8;
                int n = n0 + warp_n * 32 + nt * 8 + 2 * tg + (e & 1);
                out[(size_t)m * 768 + n] = acc[mt][nt][e] + bias[n];
            }
        }
    }
}

// ---------------------------------------------------------------------------
// Kernel 2: causal flash attention, fp32 (unchanged from R1 — known correct).
// Grid: (16 q-tiles, 96 bh). Block 256 threads.
// ---------------------------------------------------------------------------
__global__ __launch_bounds__(256) void attn_kernel()
{
    __shared__ float Qs[64][64];
    __shared__ float Kt[64][36];
    __shared__ float Vs[32][64];
    __shared__ float Ps[64][36];
    __shared__ float s_m[64], s_l[64], s_f[64];

    const int tid = threadIdx.x;
    const int qi = blockIdx.x;
    const int bh = blockIdx.y;
    const int q0 = qi * 64;
    const float* qb = g_q + (size_t)bh * 65536;
    const float* kb = g_k + (size_t)bh * 65536;
    const float* vb = g_v + (size_t)bh * 65536;

#pragma unroll
    for (int r = 0; r < 4; r++) {
        int idx = tid + r * 256;
        int q = idx >> 4, d4 = (idx & 15) * 4;
        *(float4*)&Qs[q][d4] = *(const float4*)(qb + (q0 + q) * 64 + d4);
    }
    if (tid < 64) { s_m[tid] = -1e30f; s_l[tid] = 0.0f; }

    const int tx = tid & 15, ty = tid >> 4;
    const int tk = tid & 7,  tq = tid >> 3;
    float o[4][4] = {};

    const int ktiles = (q0 >> 5) + 2;
    for (int kt = 0; kt < ktiles; kt++) {
        const int k0 = kt * 32;
        __syncthreads();
#pragma unroll
        for (int r = 0; r < 2; r++) {
            int idx = tid + r * 256;
            int kk = idx >> 4, d4 = (idx & 15) * 4;
            float4 kv = *(const float4*)(kb + (k0 + kk) * 64 + d4);
            Kt[d4 + 0][kk] = kv.x;
            Kt[d4 + 1][kk] = kv.y;
            Kt[d4 + 2][kk] = kv.z;
            Kt[d4 + 3][kk] = kv.w;
            *(float4*)&Vs[kk][d4] = *(const float4*)(vb + (k0 + kk) * 64 + d4);
        }
        __syncthreads();

        float s[2][4] = {};
#pragma unroll
        for (int d = 0; d < 64; d += 4) {
            float4 qa = *(const float4*)&Qs[2 * tq + 0][d];
            float4 qc = *(const float4*)&Qs[2 * tq + 1][d];
            float qav[4] = {qa.x, qa.y, qa.z, qa.w};
            float qcv[4] = {qc.x, qc.y, qc.z, qc.w};
#pragma unroll
            for (int dd = 0; dd < 4; dd++) {
                float4 kv = *(const float4*)&Kt[d + dd][4 * tk];
                float kf[4] = {kv.x, kv.y, kv.z, kv.w};
#pragma unroll
                for (int j = 0; j < 4; j++) {
                    s[0][j] = fmaf(qav[dd], kf[j], s[0][j]);
                    s[1][j] = fmaf(qcv[dd], kf[j], s[1][j]);
                }
            }
        }
#pragma unroll
        for (int i = 0; i < 2; i++) {
            int qg = q0 + 2 * tq + i;
#pragma unroll
            for (int j = 0; j < 4; j++) {
                int kg = k0 + 4 * tk + j;
                float v = s[i][j] * 0.125f;
                Ps[2 * tq + i][4 * tk + j] = (kg > qg) ? -1e30f : v;
            }
        }
        __syncthreads();

        if (tid < 64) {
            float mold = s_m[tid];
            float mt = mold;
#pragma unroll
            for (int kk = 0; kk < 32; kk++) mt = fmaxf(mt, Ps[tid][kk]);
            float f = __expf(mold - mt);
            float ls = 0.0f;
#pragma unroll
            for (int kk = 0; kk < 32; kk++) {
                float p = __expf(Ps[tid][kk] - mt);
                Ps[tid][kk] = p;
                ls += p;
            }
            s_m[tid] = mt;
            s_l[tid] = s_l[tid] * f + ls;
            s_f[tid] = f;
        }
        __syncthreads();

        float fr[4];
#pragma unroll
        for (int i = 0; i < 4; i++) fr[i] = s_f[4 * ty + i];
#pragma unroll
        for (int i = 0; i < 4; i++)
#pragma unroll
            for (int j = 0; j < 4; j++) o[i][j] *= fr[i];
#pragma unroll
        for (int kk = 0; kk < 32; kk++) {
            float4 vv = *(const float4*)&Vs[kk][4 * tx];
            float vf[4] = {vv.x, vv.y, vv.z, vv.w};
            float pr[4];
#pragma unroll
            for (int i = 0; i < 4; i++) pr[i] = Ps[4 * ty + i][kk];
#pragma unroll
            for (int i = 0; i < 4; i++)
#pragma unroll
                for (int j = 0; j < 4; j++)
                    o[i][j] = fmaf(pr[i], vf[j], o[i][j]);
        }
    }

    const int b = bh / 12, h = bh - b * 12;
#pragma unroll
    for (int i = 0; i < 4; i++) {
        int q = 4 * ty + i;
        float inv = 1.0f / s_l[q];
        int t = q0 + q;
        float* dst = g_y + ((size_t)(b * 1024 + t)) * 768 + h * 64 + 4 * tx;
        float4 out4 = make_float4(o[i][0] * inv, o[i][1] * inv,
                                  o[i][2] * inv, o[i][3] * inv);
        *(float4*)dst = out4;
    }
}

// ---------------------------------------------------------------------------
extern "C" void kernel_launch(void* const* d_in, const int* in_sizes, int n_in,
                              void* d_out, int out_size)
{
    const float* x      = (const float*)d_in[0];
    const float* w_attn = (const float*)d_in[1];
    const float* b_attn = (const float*)d_in[2];
    const float* w_proj = (const float*)d_in[3];
    const float* b_proj = (const float*)d_in[4];
    float* out = (float*)d_out;

    gemm_qkv_tc<<<dim3(36, 64), 256>>>(x, w_attn, b_attn);
    attn_kernel<<<dim3(16, 96), 256>>>();
    gemm_proj_tc<<<dim3(12, 64), 256>>>(w_proj, b_proj, out);
}

// round 3
// speedup vs baseline: 3.3967x; 1.7567x over previous
#include <cuda_runtime.h>
#include <cuda_bf16.h>
#include <cstdint>

// Problem constants: B=8, T=1024, C=768, H=12, HD=64
__device__ float g_q[6291456];
__device__ float g_k[6291456];
__device__ float g_v[6291456];
__device__ float g_y[6291456];

// ---------------------------------------------------------------------------
// TF32 helpers
// ---------------------------------------------------------------------------
__device__ __forceinline__ float to_tf32(float x) {
    uint32_t u;
    asm("cvt.rna.tf32.f32 %0, %1;" : "=r"(u) : "f"(x));
    return __uint_as_float(u);
}

__device__ __forceinline__ void mma_tf32(float* c, const uint32_t* a, const uint32_t* b) {
    asm volatile(
        "mma.sync.aligned.m16n8k8.row.col.f32.tf32.tf32.f32 "
        "{%0,%1,%2,%3},{%4,%5,%6,%7},{%8,%9},{%0,%1,%2,%3};"
        : "+f"(c[0]), "+f"(c[1]), "+f"(c[2]), "+f"(c[3])
        : "r"(a[0]), "r"(a[1]), "r"(a[2]), "r"(a[3]), "r"(b[0]), "r"(b[1]));
}

// ---------------------------------------------------------------------------
// TF32 GEMM body (unchanged from R2): 128x64 block tile, K-step 32, 8 warps.
// ---------------------------------------------------------------------------
#define GEMM_TF32_BODY(APTR, LDA, BPTR, LDB, KDIM)                              \
    __shared__ float As[128][36];                                               \
    __shared__ float Bs[32][72];                                                \
    const int tid  = threadIdx.x;                                               \
    const int lane = tid & 31;                                                  \
    const int wid  = tid >> 5;                                                  \
    const int warp_m = wid >> 1, warp_n = wid & 1;                              \
    const int g = lane >> 2, tg = lane & 3;                                     \
    const int m0 = blockIdx.y * 128, n0 = blockIdx.x * 64;                      \
    float acc[2][4][4] = {};                                                    \
    const int a_row = tid >> 3, a_col = (tid & 7) * 4;                          \
    const int b_row = tid >> 4, b_col = (tid & 15) * 4;                         \
    for (int k0 = 0; k0 < (KDIM); k0 += 32) {                                   \
        float4 av[4];                                                           \
        _Pragma("unroll")                                                       \
        for (int r = 0; r < 4; r++)                                             \
            av[r] = *(const float4*)((APTR) + (size_t)(m0 + r * 32 + a_row) * (LDA) + k0 + a_col); \
        float4 bv[2];                                                           \
        _Pragma("unroll")                                                       \
        for (int r = 0; r < 2; r++)                                             \
            bv[r] = *(const float4*)((BPTR) + (size_t)(k0 + r * 16 + b_row) * (LDB) + n0 + b_col); \
        __syncthreads();                                                        \
        _Pragma("unroll")                                                       \
        for (int r = 0; r < 4; r++) {                                           \
            float* dst = &As[r * 32 + a_row][a_col];                            \
            dst[0] = to_tf32(av[r].x); dst[1] = to_tf32(av[r].y);               \
            dst[2] = to_tf32(av[r].z); dst[3] = to_tf32(av[r].w);               \
        }                                                                       \
        _Pragma("unroll")                                                       \
        for (int r = 0; r < 2; r++) {                                           \
            float* dst = &Bs[r * 16 + b_row][b_col];                            \
            dst[0] = to_tf32(bv[r].x); dst[1] = to_tf32(bv[r].y);               \
            dst[2] = to_tf32(bv[r].z); dst[3] = to_tf32(bv[r].w);               \
        }                                                                       \
        __syncthreads();                                                        \
        _Pragma("unroll")                                                       \
        for (int ks = 0; ks < 4; ks++) {                                        \
            const int kk = ks * 8;                                              \
            uint32_t afr[2][4], bfr[4][2];                                      \
            _Pragma("unroll")                                                   \
            for (int mt = 0; mt < 2; mt++) {                                    \
                const int mr = warp_m * 32 + mt * 16;                           \
                afr[mt][0] = __float_as_uint(As[mr + g][kk + tg]);              \
                afr[mt][1] = __float_as_uint(As[mr + g + 8][kk + tg]);          \
                afr[mt][2] = __float_as_uint(As[mr + g][kk + tg + 4]);          \
                afr[mt][3] = __float_as_uint(As[mr + g + 8][kk + tg + 4]);      \
            }                                                                   \
            _Pragma("unroll")                                                   \
            for (int nt = 0; nt < 4; nt++) {                                    \
                const int nc = warp_n * 32 + nt * 8;                            \
                bfr[nt][0] = __float_as_uint(Bs[kk + tg][nc + g]);              \
                bfr[nt][1] = __float_as_uint(Bs[kk + tg + 4][nc + g]);          \
            }                                                                   \
            _Pragma("unroll")                                                   \
            for (int mt = 0; mt < 2; mt++)                                      \
                _Pragma("unroll")                                               \
                for (int nt = 0; nt < 4; nt++)                                  \
                    mma_tf32(acc[mt][nt], afr[mt], bfr[nt]);                    \
        }                                                                       \
    }

// ---------------------------------------------------------------------------
// Kernel 1: QKV GEMM, scatter epilogue into q/k/v [B,H,T,64] with bias.
// ---------------------------------------------------------------------------
__global__ __launch_bounds__(256) void gemm_qkv_tc(
    const float* __restrict__ x, const float* __restrict__ w,
    const float* __restrict__ bias)
{
    GEMM_TF32_BODY(x, 768, w, 2304, 768)

#pragma unroll
    for (int mt = 0; mt < 2; mt++) {
#pragma unroll
        for (int nt = 0; nt < 4; nt++) {
#pragma unroll
            for (int e = 0; e < 4; e++) {
                int m = m0 + warp_m * 32 + mt * 16 + g + (e >> 1) * 8;
                int n = n0 + warp_n * 32 + nt * 8 + 2 * tg + (e & 1);
                float v = acc[mt][nt][e] + bias[n];
                int bb = m >> 10, t = m & 1023;
                int which = n / 768;
                int c = n - which * 768;
                int hh = c >> 6, d = c & 63;
                float* dst = (which == 0) ? g_q : (which == 1) ? g_k : g_v;
                dst[((((size_t)bb * 12 + hh) << 10) + t) * 64 + d] = v;
            }
        }
    }
}

// ---------------------------------------------------------------------------
// Kernel 3: output projection, reads g_y, writes d_out.
// ---------------------------------------------------------------------------
__global__ __launch_bounds__(256) void gemm_proj_tc(
    const float* __restrict__ w, const float* __restrict__ bias,
    float* __restrict__ out)
{
    GEMM_TF32_BODY(g_y, 768, w, 768, 768)

#pragma unroll
    for (int mt = 0; mt < 2; mt++) {
#pragma unroll
        for (int nt = 0; nt < 4; nt++) {
#pragma unroll
            for (int e = 0; e < 4; e++) {
                int m = m0 + warp_m * 32 + mt * 16 + g + (e >> 1) * 8;
                int n = n0 + warp_n * 32 + nt * 8 + 2 * tg + (e & 1);
                out[(size_t)m * 768 + n] = acc[mt][nt][e] + bias[n];
            }
        }
    }
}

// ---------------------------------------------------------------------------
// Kernel 2: causal flash attention with TF32 tensor cores.
// Grid (16 q-tiles, 96 bh), 256 threads = 8 warps (4m x 2n).
// Q tile 64x64, K/V tiles 32x64. Online softmax in fp32.
// Smem pitches chosen for conflict-free MMA fragment loads:
//   Qs/Ks pitch 68 -> (4g+tg)%32 bijective; Vs pitch 72 -> (8tg+g)%32;
//   Ps pitch 36 -> (4g+tg)%32.
// ---------------------------------------------------------------------------
__global__ __launch_bounds__(256) void attn_tc_kernel()
{
    __shared__ float Qs[64][68];
    __shared__ float Ks[32][68];
    __shared__ float Vs[32][72];
    __shared__ float Ps[64][36];
    __shared__ float s_m[64], s_l[64], s_f[64];

    const int tid = threadIdx.x;
    const int lane = tid & 31;
    const int wid = tid >> 5;
    const int warp_m = wid >> 1, warp_n = wid & 1;
    const int g = lane >> 2, tg = lane & 3;
    const int qi = blockIdx.x, bh = blockIdx.y;
    const int q0 = qi * 64;
    const float* qb = g_q + (size_t)bh * 65536;
    const float* kb = g_k + (size_t)bh * 65536;
    const float* vb = g_v + (size_t)bh * 65536;
    const int mr = warp_m * 16;

    // Load Q tile (tf32)
#pragma unroll
    for (int r = 0; r < 4; r++) {
        int idx = tid + r * 256;
        int q = idx >> 4, d4 = (idx & 15) * 4;
        float4 v4 = *(const float4*)(qb + (size_t)(q0 + q) * 64 + d4);
        float* dst = &Qs[q][d4];
        dst[0] = to_tf32(v4.x); dst[1] = to_tf32(v4.y);
        dst[2] = to_tf32(v4.z); dst[3] = to_tf32(v4.w);
    }
    if (tid < 64) { s_m[tid] = -1e30f; s_l[tid] = 0.0f; }

    float acc_o[4][4] = {};

    const int ktiles = 2 * qi + 2;
    for (int kt = 0; kt < ktiles; kt++) {
        const int k0 = kt * 32;

        // gmem loads into regs (before the sync so they overlap prior phase)
        float4 kv[2], vv[2];
#pragma unroll
        for (int r = 0; r < 2; r++) {
            int idx = tid + r * 256;
            int kk = idx >> 4, d4 = (idx & 15) * 4;
            kv[r] = *(const float4*)(kb + (size_t)(k0 + kk) * 64 + d4);
            vv[r] = *(const float4*)(vb + (size_t)(k0 + kk) * 64 + d4);
        }
        __syncthreads();   // prior iteration's PV reads of Ps/Vs done
#pragma unroll
        for (int r = 0; r < 2; r++) {
            int idx = tid + r * 256;
            int kk = idx >> 4, d4 = (idx & 15) * 4;
            float* kd = &Ks[kk][d4];
            kd[0] = to_tf32(kv[r].x); kd[1] = to_tf32(kv[r].y);
            kd[2] = to_tf32(kv[r].z); kd[3] = to_tf32(kv[r].w);
            float* vd = &Vs[kk][d4];
            vd[0] = to_tf32(vv[r].x); vd[1] = to_tf32(vv[r].y);
            vd[2] = to_tf32(vv[r].z); vd[3] = to_tf32(vv[r].w);
        }
        __syncthreads();

        // ---- S = Q K^T (warp tile 16x32) ----
        float acc_s[2][4] = {};
#pragma unroll
        for (int ks = 0; ks < 8; ks++) {
            const int kk = ks * 8;
            uint32_t afr[4];
            afr[0] = __float_as_uint(Qs[mr + g][kk + tg]);
            afr[1] = __float_as_uint(Qs[mr + g + 8][kk + tg]);
            afr[2] = __float_as_uint(Qs[mr + g][kk + tg + 4]);
            afr[3] = __float_as_uint(Qs[mr + g + 8][kk + tg + 4]);
#pragma unroll
            for (int nt = 0; nt < 2; nt++) {
                const int nc = warp_n * 16 + nt * 8;
                uint32_t bfr[2];
                bfr[0] = __float_as_uint(Ks[nc + g][kk + tg]);
                bfr[1] = __float_as_uint(Ks[nc + g][kk + tg + 4]);
                mma_tf32(acc_s[nt], afr, bfr);
            }
        }
        // mask + scale -> Ps
#pragma unroll
        for (int nt = 0; nt < 2; nt++) {
            const int nc = warp_n * 16 + nt * 8;
#pragma unroll
            for (int e = 0; e < 4; e++) {
                int row = mr + g + (e >> 1) * 8;
                int col = nc + 2 * tg + (e & 1);
                int qg = q0 + row, kg = k0 + col;
                Ps[row][col] = (kg > qg) ? -1e30f : acc_s[nt][e] * 0.125f;
            }
        }
        __syncthreads();

        // ---- online softmax: 4 threads per row ----
        {
            const int row = tid >> 2, sub = tid & 3;
            float mold = s_m[row];
            float mt = mold;
            float vals[8];
#pragma unroll
            for (int j = 0; j < 8; j++) {
                vals[j] = Ps[row][sub * 8 + j];
                mt = fmaxf(mt, vals[j]);
            }
            mt = fmaxf(mt, __shfl_xor_sync(0xffffffffu, mt, 1));
            mt = fmaxf(mt, __shfl_xor_sync(0xffffffffu, mt, 2));
            float ls = 0.0f;
#pragma unroll
            for (int j = 0; j < 8; j++) {
                float p = __expf(vals[j] - mt);
                Ps[row][sub * 8 + j] = to_tf32(p);
                ls += p;
            }
            ls += __shfl_xor_sync(0xffffffffu, ls, 1);
            ls += __shfl_xor_sync(0xffffffffu, ls, 2);
            if (sub == 0) {
                float f = __expf(mold - mt);
                s_m[row] = mt;
                s_l[row] = s_l[row] * f + ls;
                s_f[row] = f;
            }
        }
        __syncthreads();

        // ---- rescale O and accumulate P @ V (warp tile 16x32) ----
        float f0 = s_f[mr + g], f1 = s_f[mr + g + 8];
#pragma unroll
        for (int nt = 0; nt < 4; nt++) {
            acc_o[nt][0] *= f0; acc_o[nt][1] *= f0;
            acc_o[nt][2] *= f1; acc_o[nt][3] *= f1;
        }
#pragma unroll
        for (int ks = 0; ks < 4; ks++) {
            const int kk = ks * 8;
            uint32_t afr[4];
            afr[0] = __float_as_uint(Ps[mr + g][kk + tg]);
            afr[1] = __float_as_uint(Ps[mr + g + 8][kk + tg]);
            afr[2] = __float_as_uint(Ps[mr + g][kk + tg + 4]);
            afr[3] = __float_as_uint(Ps[mr + g + 8][kk + tg + 4]);
#pragma unroll
            for (int nt = 0; nt < 4; nt++) {
                const int nc = warp_n * 32 + nt * 8;
                uint32_t bfr[2];
                bfr[0] = __float_as_uint(Vs[kk + tg][nc + g]);
                bfr[1] = __float_as_uint(Vs[kk + tg + 4][nc + g]);
                mma_tf32(acc_o[nt], afr, bfr);
            }
        }
    }

    // ---- epilogue: normalize, write g_y in [B,T,C] layout ----
    const int b = bh / 12, h = bh - b * 12;
    float inv0 = 1.0f / s_l[mr + g];
    float inv1 = 1.0f / s_l[mr + g + 8];
    const int t0 = q0 + mr + g, t1 = t0 + 8;
#pragma unroll
    for (int nt = 0; nt < 4; nt++) {
        int col = warp_n * 32 + nt * 8 + 2 * tg;
        float* d0 = g_y + ((size_t)(b * 1024 + t0)) * 768 + h * 64 + col;
        float* d1 = g_y + ((size_t)(b * 1024 + t1)) * 768 + h * 64 + col;
        *(float2*)d0 = make_float2(acc_o[nt][0] * inv0, acc_o[nt][1] * inv0);
        *(float2*)d1 = make_float2(acc_o[nt][2] * inv1, acc_o[nt][3] * inv1);
    }
}

// ---------------------------------------------------------------------------
extern "C" void kernel_launch(void* const* d_in, const int* in_sizes, int n_in,
                              void* d_out, int out_size)
{
    const float* x      = (const float*)d_in[0];
    const float* w_attn = (const float*)d_in[1];
    const float* b_attn = (const float*)d_in[2];
    const float* w_proj = (const float*)d_in[3];
    const float* b_proj = (const float*)d_in[4];
    float* out = (float*)d_out;

    gemm_qkv_tc<<<dim3(36, 64), 256>>>(x, w_attn, b_attn);
    attn_tc_kernel<<<dim3(16, 96), 256>>>();
    gemm_proj_tc<<<dim3(12, 64), 256>>>(w_proj, b_proj, out);
}

// round 4
// speedup vs baseline: 3.5994x; 1.0597x over previous
#include <cuda_runtime.h>
#include <cuda_bf16.h>
#include <cstdint>

// Problem constants: B=8, T=1024, C=768, H=12, HD=64
__device__ float g_q[6291456];
__device__ float g_k[6291456];
__device__ float g_v[6291456];
__device__ float g_y[6291456];

// ---------------------------------------------------------------------------
// helpers
// ---------------------------------------------------------------------------
__device__ __forceinline__ float to_tf32(float x) {
    uint32_t u;
    asm("cvt.rna.tf32.f32 %0, %1;" : "=r"(u) : "f"(x));
    return __uint_as_float(u);
}
__device__ __forceinline__ uint32_t tf32b(float x) {
    uint32_t u;
    asm("cvt.rna.tf32.f32 %0, %1;" : "=r"(u) : "f"(x));
    return u;
}
__device__ __forceinline__ void mma_tf32(float* c, const uint32_t* a, const uint32_t* b) {
    asm volatile(
        "mma.sync.aligned.m16n8k8.row.col.f32.tf32.tf32.f32 "
        "{%0,%1,%2,%3},{%4,%5,%6,%7},{%8,%9},{%0,%1,%2,%3};"
        : "+f"(c[0]), "+f"(c[1]), "+f"(c[2]), "+f"(c[3])
        : "r"(a[0]), "r"(a[1]), "r"(a[2]), "r"(a[3]), "r"(b[0]), "r"(b[1]));
}
__device__ __forceinline__ uint32_t smem_u32(const void* p) {
    return (uint32_t)__cvta_generic_to_shared(p);
}
#define CP_ASYNC16(dst, src) \
    asm volatile("cp.async.cg.shared.global [%0], [%1], 16;\n" :: "r"(dst), "l"(src))
#define CP_COMMIT() asm volatile("cp.async.commit_group;\n")
#define CP_WAIT(N)  asm volatile("cp.async.wait_group %0;\n" :: "n"(N))

// ---------------------------------------------------------------------------
// TF32 GEMM: block tile 128x128, 4 warps (2x2), warp tile 64x64, K-step 16,
// 2-stage cp.async double buffering.  K = 768 fixed (48 steps).
//   As pitch 20 -> A-frag banks (4g+tg)%32 bijective, conflict-free
//   Bs pitch 136 -> B-frag banks (8tg+g)%32 bijective, conflict-free
//   cp.async 16B chunks, raw fp32; cvt.rna at fragment load.
// ---------------------------------------------------------------------------
#define GEMM128_LOAD(S, K0, APTR, LDA, BPTR, LDB)                               \
    _Pragma("unroll")                                                           \
    for (int i = 0; i < 4; i++) {                                               \
        int r = a_r + i * 32;                                                   \
        CP_ASYNC16(smem_u32(&As[S][r][a_c]),                                    \
                   (APTR) + (size_t)(m0 + r) * (LDA) + (K0) + a_c);             \
    }                                                                           \
    _Pragma("unroll")                                                           \
    for (int i = 0; i < 4; i++) {                                               \
        int r = b_r + i * 4;                                                    \
        CP_ASYNC16(smem_u32(&Bs[S][r][b_c]),                                    \
                   (BPTR) + (size_t)((K0) + r) * (LDB) + n0 + b_c);             \
    }                                                                           \
    CP_COMMIT();

#define GEMM128_BODY(APTR, LDA, BPTR, LDB)                                      \
    __shared__ float As[2][128][20];                                            \
    __shared__ float Bs[2][16][136];                                            \
    const int tid  = threadIdx.x;                                               \
    const int lane = tid & 31;                                                  \
    const int wid  = tid >> 5;                                                  \
    const int warp_m = wid >> 1, warp_n = wid & 1;                              \
    const int g = lane >> 2, tg = lane & 3;                                     \
    const int m0 = blockIdx.y * 128, n0 = blockIdx.x * 128;                     \
    const int a_r = tid >> 2, a_c = (tid & 3) * 4;                              \
    const int b_r = tid >> 5, b_c = (tid & 31) * 4;                             \
    float acc[4][8][4] = {};                                                    \
    GEMM128_LOAD(0, 0, APTR, LDA, BPTR, LDB)                                    \
    for (int step = 0; step < 48; step++) {                                     \
        const int s = step & 1;                                                 \
        if (step + 1 < 48) {                                                    \
            GEMM128_LOAD(s ^ 1, (step + 1) * 16, APTR, LDA, BPTR, LDB)          \
            CP_WAIT(1);                                                         \
        } else {                                                                \
            CP_WAIT(0);                                                         \
        }                                                                       \
        __syncthreads();                                                        \
        _Pragma("unroll")                                                       \
        for (int ks = 0; ks < 2; ks++) {                                        \
            const int kk = ks * 8;                                              \
            uint32_t afr[4][4], bfr[8][2];                                      \
            _Pragma("unroll")                                                   \
            for (int mt = 0; mt < 4; mt++) {                                    \
                const int rb = warp_m * 64 + mt * 16;                           \
                afr[mt][0] = tf32b(As[s][rb + g][kk + tg]);                     \
                afr[mt][1] = tf32b(As[s][rb + g + 8][kk + tg]);                 \
                afr[mt][2] = tf32b(As[s][rb + g][kk + tg + 4]);                 \
                afr[mt][3] = tf32b(As[s][rb + g + 8][kk + tg + 4]);             \
            }                                                                   \
            _Pragma("unroll")                                                   \
            for (int nt = 0; nt < 8; nt++) {                                    \
                const int cb = warp_n * 64 + nt * 8;                            \
                bfr[nt][0] = tf32b(Bs[s][kk + tg][cb + g]);                     \
                bfr[nt][1] = tf32b(Bs[s][kk + tg + 4][cb + g]);                 \
            }                                                                   \
            _Pragma("unroll")                                                   \
            for (int mt = 0; mt < 4; mt++)                                      \
                _Pragma("unroll")                                               \
                for (int nt = 0; nt < 8; nt++)                                  \
                    mma_tf32(acc[mt][nt], afr[mt], bfr[nt]);                    \
        }                                                                       \
        __syncthreads();                                                        \
    }

// ---------------------------------------------------------------------------
// Kernel 1: QKV GEMM (M=8192, N=2304, K=768), scatter epilogue into
// q/k/v [B,H,T,64] with bias.
// ---------------------------------------------------------------------------
__global__ __launch_bounds__(128) void gemm_qkv_tc(
    const float* __restrict__ x, const float* __restrict__ w,
    const float* __restrict__ bias)
{
    GEMM128_BODY(x, 768, w, 2304)

#pragma unroll
    for (int mt = 0; mt < 4; mt++) {
#pragma unroll
        for (int nt = 0; nt < 8; nt++) {
#pragma unroll
            for (int e = 0; e < 4; e++) {
                int m = m0 + warp_m * 64 + mt * 16 + g + (e >> 1) * 8;
                int n = n0 + warp_n * 64 + nt * 8 + 2 * tg + (e & 1);
                float v = acc[mt][nt][e] + bias[n];
                int bb = m >> 10, t = m & 1023;
                int which = n / 768;
                int c = n - which * 768;
                int hh = c >> 6, d = c & 63;
                float* dst = (which == 0) ? g_q : (which == 1) ? g_k : g_v;
                dst[((((size_t)bb * 12 + hh) << 10) + t) * 64 + d] = v;
            }
        }
    }
}

// ---------------------------------------------------------------------------
// Kernel 3: output projection (M=8192, N=768, K=768), reads g_y -> d_out.
// ---------------------------------------------------------------------------
__global__ __launch_bounds__(128) void gemm_proj_tc(
    const float* __restrict__ w, const float* __restrict__ bias,
    float* __restrict__ out)
{
    GEMM128_BODY(g_y, 768, w, 768)

#pragma unroll
    for (int mt = 0; mt < 4; mt++) {
#pragma unroll
        for (int nt = 0; nt < 8; nt++) {
#pragma unroll
            for (int e = 0; e < 4; e++) {
                int m = m0 + warp_m * 64 + mt * 16 + g + (e >> 1) * 8;
                int n = n0 + warp_n * 64 + nt * 8 + 2 * tg + (e & 1);
                out[(size_t)m * 768 + n] = acc[mt][nt][e] + bias[n];
            }
        }
    }
}

// ---------------------------------------------------------------------------
// Kernel 2: causal flash attention with TF32 tensor cores (unchanged, R3).
// ---------------------------------------------------------------------------
__global__ __launch_bounds__(256) void attn_tc_kernel()
{
    __shared__ float Qs[64][68];
    __shared__ float Ks[32][68];
    __shared__ float Vs[32][72];
    __shared__ float Ps[64][36];
    __shared__ float s_m[64], s_l[64], s_f[64];

    const int tid = threadIdx.x;
    const int lane = tid & 31;
    const int wid = tid >> 5;
    const int warp_m = wid >> 1, warp_n = wid & 1;
    const int g = lane >> 2, tg = lane & 3;
    const int qi = blockIdx.x, bh = blockIdx.y;
    const int q0 = qi * 64;
    const float* qb = g_q + (size_t)bh * 65536;
    const float* kb = g_k + (size_t)bh * 65536;
    const float* vb = g_v + (size_t)bh * 65536;
    const int mr = warp_m * 16;

#pragma unroll
    for (int r = 0; r < 4; r++) {
        int idx = tid + r * 256;
        int q = idx >> 4, d4 = (idx & 15) * 4;
        float4 v4 = *(const float4*)(qb + (size_t)(q0 + q) * 64 + d4);
        float* dst = &Qs[q][d4];
        dst[0] = to_tf32(v4.x); dst[1] = to_tf32(v4.y);
        dst[2] = to_tf32(v4.z); dst[3] = to_tf32(v4.w);
    }
    if (tid < 64) { s_m[tid] = -1e30f; s_l[tid] = 0.0f; }

    float acc_o[4][4] = {};

    const int ktiles = 2 * qi + 2;
    for (int kt = 0; kt < ktiles; kt++) {
        const int k0 = kt * 32;

        float4 kv[2], vv[2];
#pragma unroll
        for (int r = 0; r < 2; r++) {
            int idx = tid + r * 256;
            int kk = idx >> 4, d4 = (idx & 15) * 4;
            kv[r] = *(const float4*)(kb + (size_t)(k0 + kk) * 64 + d4);
            vv[r] = *(const float4*)(vb + (size_t)(k0 + kk) * 64 + d4);
        }
        __syncthreads();
#pragma unroll
        for (int r = 0; r < 2; r++) {
            int idx = tid + r * 256;
            int kk = idx >> 4, d4 = (idx & 15) * 4;
            float* kd = &Ks[kk][d4];
            kd[0] = to_tf32(kv[r].x); kd[1] = to_tf32(kv[r].y);
            kd[2] = to_tf32(kv[r].z); kd[3] = to_tf32(kv[r].w);
            float* vd = &Vs[kk][d4];
            vd[0] = to_tf32(vv[r].x); vd[1] = to_tf32(vv[r].y);
            vd[2] = to_tf32(vv[r].z); vd[3] = to_tf32(vv[r].w);
        }
        __syncthreads();

        float acc_s[2][4] = {};
#pragma unroll
        for (int ks = 0; ks < 8; ks++) {
            const int kk = ks * 8;
            uint32_t afr[4];
            afr[0] = __float_as_uint(Qs[mr + g][kk + tg]);
            afr[1] = __float_as_uint(Qs[mr + g + 8][kk + tg]);
            afr[2] = __float_as_uint(Qs[mr + g][kk + tg + 4]);
            afr[3] = __float_as_uint(Qs[mr + g + 8][kk + tg + 4]);
#pragma unroll
            for (int nt = 0; nt < 2; nt++) {
                const int nc = warp_n * 16 + nt * 8;
                uint32_t bfr[2];
                bfr[0] = __float_as_uint(Ks[nc + g][kk + tg]);
                bfr[1] = __float_as_uint(Ks[nc + g][kk + tg + 4]);
                mma_tf32(acc_s[nt], afr, bfr);
            }
        }
#pragma unroll
        for (int nt = 0; nt < 2; nt++) {
            const int nc = warp_n * 16 + nt * 8;
#pragma unroll
            for (int e = 0; e < 4; e++) {
                int row = mr + g + (e >> 1) * 8;
                int col = nc + 2 * tg + (e & 1);
                int qg = q0 + row, kg = k0 + col;
                Ps[row][col] = (kg > qg) ? -1e30f : acc_s[nt][e] * 0.125f;
            }
        }
        __syncthreads();

        {
            const int row = tid >> 2, sub = tid & 3;
            float mold = s_m[row];
            float mt = mold;
            float vals[8];
#pragma unroll
            for (int j = 0; j < 8; j++) {
                vals[j] = Ps[row][sub * 8 + j];
                mt = fmaxf(mt, vals[j]);
            }
            mt = fmaxf(mt, __shfl_xor_sync(0xffffffffu, mt, 1));
            mt = fmaxf(mt, __shfl_xor_sync(0xffffffffu, mt, 2));
            float ls = 0.0f;
#pragma unroll
            for (int j = 0; j < 8; j++) {
                float p = __expf(vals[j] - mt);
                Ps[row][sub * 8 + j] = to_tf32(p);
                ls += p;
            }
            ls += __shfl_xor_sync(0xffffffffu, ls, 1);
            ls += __shfl_xor_sync(0xffffffffu, ls, 2);
            if (sub == 0) {
                float f = __expf(mold - mt);
                s_m[row] = mt;
                s_l[row] = s_l[row] * f + ls;
                s_f[row] = f;
            }
        }
        __syncthreads();

        float f0 = s_f[mr + g], f1 = s_f[mr + g + 8];
#pragma unroll
        for (int nt = 0; nt < 4; nt++) {
            acc_o[nt][0] *= f0; acc_o[nt][1] *= f0;
            acc_o[nt][2] *= f1; acc_o[nt][3] *= f1;
        }
#pragma unroll
        for (int ks = 0; ks < 4; ks++) {
            const int kk = ks * 8;
            uint32_t afr[4];
            afr[0] = __float_as_uint(Ps[mr + g][kk + tg]);
            afr[1] = __float_as_uint(Ps[mr + g + 8][kk + tg]);
            afr[2] = __float_as_uint(Ps[mr + g][kk + tg + 4]);
            afr[3] = __float_as_uint(Ps[mr + g + 8][kk + tg + 4]);
#pragma unroll
            for (int nt = 0; nt < 4; nt++) {
                const int nc = warp_n * 32 + nt * 8;
                uint32_t bfr[2];
                bfr[0] = __float_as_uint(Vs[kk + tg][nc + g]);
                bfr[1] = __float_as_uint(Vs[kk + tg + 4][nc + g]);
                mma_tf32(acc_o[nt], afr, bfr);
            }
        }
    }

    const int b = bh / 12, h = bh - b * 12;
    float inv0 = 1.0f / s_l[mr + g];
    float inv1 = 1.0f / s_l[mr + g + 8];
    const int t0 = q0 + mr + g, t1 = t0 + 8;
#pragma unroll
    for (int nt = 0; nt < 4; nt++) {
        int col = warp_n * 32 + nt * 8 + 2 * tg;
        float* d0 = g_y + ((size_t)(b * 1024 + t0)) * 768 + h * 64 + col;
        float* d1 = g_y + ((size_t)(b * 1024 + t1)) * 768 + h * 64 + col;
        *(float2*)d0 = make_float2(acc_o[nt][0] * inv0, acc_o[nt][1] * inv0);
        *(float2*)d1 = make_float2(acc_o[nt][2] * inv1, acc_o[nt][3] * inv1);
    }
}

// ---------------------------------------------------------------------------
extern "C" void kernel_launch(void* const* d_in, const int* in_sizes, int n_in,
                              void* d_out, int out_size)
{
    const float* x      = (const float*)d_in[0];
    const float* w_attn = (const float*)d_in[1];
    const float* b_attn = (const float*)d_in[2];
    const float* w_proj = (const float*)d_in[3];
    const float* b_proj = (const float*)d_in[4];
    float* out = (float*)d_out;

    gemm_qkv_tc<<<dim3(18, 64), 128>>>(x, w_attn, b_attn);
    attn_tc_kernel<<<dim3(16, 96), 256>>>();
    gemm_proj_tc<<<dim3(6, 64), 128>>>(w_proj, b_proj, out);
}